// round 1
// baseline (speedup 1.0000x reference)
#include <cuda_runtime.h>

// QuietAttention (softmax_one attention with sink token) — fp32 baseline.
//
// Shapes: q,k,v [B=16, S=2048, D=128] fp32; mask [B,S,S] int32.
// Outputs: out [B,S,D] then p_attn [B,S,S+1], concatenated in d_out.
//
// Strategy: one block per (batch, 128-query tile). Block owns its rows
// end-to-end:
//   P0: load Q tile to smem
//   P1: QK^T GEMM (128x128 C-tiles, 8x8 register blocking), scale, mask,
//       track row max, stage RAW scores into the p_attn gmem region.
//   P2: row Z = sum exp(s - m) (reads staged scores; block-local, so
//       __syncthreads suffices for visibility). inv = 1/(1+Z). sink col.
//   P3: re-read staged scores, p = exp(s-m)*inv, write final p, and
//       accumulate out += p @ V (second 8x8-blocked GEMM).

#define BB 16
#define SS 2048
#define DD 128
#define SP1 (SS + 1)
#define TQ 128
#define TK 128
#define NTHREADS 256
#define PITCH 129   // smem row pitch (bank-conflict padding)

// smem floats: sA(128*129) + sB(128*129) + sRed(128*16) + sM(128) + sZ(128) + sInv(128)
#define SMEM_FLOATS (2 * 128 * PITCH + 128 * 16 + 3 * 128)
#define SMEM_BYTES (SMEM_FLOATS * 4)

__global__ __launch_bounds__(NTHREADS, 1)
void qa_fp32_kernel(const float* __restrict__ q,
                    const float* __restrict__ k,
                    const float* __restrict__ v,
                    const int* __restrict__ mask,
                    float* __restrict__ out,
                    float* __restrict__ p,
                    int write_out)
{
    extern __shared__ float sm[];
    float* sA   = sm;                     // [128][PITCH]  Q tile, later E tile (transposed)
    float* sB   = sA + 128 * PITCH;       // [128][PITCH]  K tile, later V tile
    float* sRed = sB + 128 * PITCH;       // [128][16] rowmax reduction
    float* sM   = sRed + 128 * 16;        // [128]
    float* sZ   = sM + 128;               // [128]
    float* sInv = sZ + 128;               // [128]

    const int b     = blockIdx.y;
    const int qbase = blockIdx.x * TQ;
    const int tid   = threadIdx.x;
    const int tx    = tid & 15;           // 0..15
    const int ty    = tid >> 4;           // 0..15

    const float* qb = q + ((size_t)b * SS + qbase) * DD;
    const float* kb = k + (size_t)b * SS * DD;
    const float* vb = v + (size_t)b * SS * DD;
    const int*   mb = mask + ((size_t)b * SS + qbase) * SS;
    float*       pb = p + ((size_t)b * SS + qbase) * SP1;
    float*       ob = out + ((size_t)b * SS + qbase) * DD;

    // ---- P0: load Q tile [r][d] ----
    for (int n = tid; n < TQ * DD; n += NTHREADS) {
        int r = n >> 7, d = n & 127;
        sA[r * PITCH + d] = qb[n];
    }
    if (tid < 128) sZ[tid] = 0.0f;

    float rmax[8];
#pragma unroll
    for (int i = 0; i < 8; i++) rmax[i] = -3.0e38f;

    const float scale = 0.08838834764831845f;  // 1/sqrt(128)

    // ---- P1: QK^T, mask, rowmax, stage scores ----
    for (int kt = 0; kt < SS / TK; ++kt) {
        __syncthreads();
        const float* ksrc = kb + (size_t)kt * TK * DD;
        for (int n = tid; n < TK * DD; n += NTHREADS) {
            int c = n >> 7, d = n & 127;
            sB[c * PITCH + d] = ksrc[n];
        }
        __syncthreads();

        float acc[8][8];
#pragma unroll
        for (int i = 0; i < 8; i++)
#pragma unroll
            for (int j = 0; j < 8; j++) acc[i][j] = 0.0f;

#pragma unroll 4
        for (int d = 0; d < DD; ++d) {
            float a[8], bv[8];
#pragma unroll
            for (int i = 0; i < 8; i++) a[i] = sA[(ty + 16 * i) * PITCH + d];
#pragma unroll
            for (int j = 0; j < 8; j++) bv[j] = sB[(tx + 16 * j) * PITCH + d];
#pragma unroll
            for (int i = 0; i < 8; i++)
#pragma unroll
                for (int j = 0; j < 8; j++)
                    acc[i][j] = fmaf(a[i], bv[j], acc[i][j]);
        }

        // epilogue: scale, mask, max, store raw scores at p[.., 1+c]
#pragma unroll
        for (int i = 0; i < 8; i++) {
            int r = ty + 16 * i;
            const int* mrow = mb + (size_t)r * SS + kt * TK;
            float* prow = pb + (size_t)r * SP1 + 1 + kt * TK;
#pragma unroll
            for (int j = 0; j < 8; j++) {
                int c = tx + 16 * j;
                float s = (mrow[c] == 0) ? -1e9f : acc[i][j] * scale;
                rmax[i] = fmaxf(rmax[i], s);
                prow[c] = s;
            }
        }
    }

    // ---- P1b: reduce row max across tx ----
    __syncthreads();
#pragma unroll
    for (int i = 0; i < 8; i++) sRed[(ty + 16 * i) * 16 + tx] = rmax[i];
    __syncthreads();
    if (tid < 128) {
        float m = -3.0e38f;
#pragma unroll
        for (int t = 0; t < 16; t++) m = fmaxf(m, sRed[tid * 16 + t]);
        sM[tid] = m;
    }
    __syncthreads();

    // ---- P2: Z = sum exp(s - m) per row ----
    for (int r = 0; r < TQ; ++r) {
        const float m = sM[r];
        const float* prow = pb + (size_t)r * SP1 + 1;
        float zp = 0.0f;
        for (int c = tid; c < SS; c += NTHREADS)
            zp += __expf(prow[c] - m);
#pragma unroll
        for (int o = 16; o > 0; o >>= 1)
            zp += __shfl_xor_sync(0xffffffffu, zp, o);
        if ((tid & 31) == 0) atomicAdd(&sZ[r], zp);
    }
    __syncthreads();
    if (tid < 128) {
        float inv = 1.0f / (1.0f + sZ[tid]);
        sInv[tid] = inv;
        // sink column: exp(-1e9 - m) * inv  (0 unless the whole row is masked)
        pb[(size_t)tid * SP1] = __expf(-1e9f - sM[tid]) * inv;
    }

    // ---- P3: finalize p and accumulate out = p @ V ----
    float oacc[8][8];
#pragma unroll
    for (int i = 0; i < 8; i++)
#pragma unroll
        for (int j = 0; j < 8; j++) oacc[i][j] = 0.0f;

    for (int kt = 0; kt < SS / TK; ++kt) {
        __syncthreads();
        // V tile natural [kc][d]
        const float* vsrc = vb + (size_t)kt * TK * DD;
        for (int n = tid; n < TK * DD; n += NTHREADS) {
            int kc = n >> 7, d = n & 127;
            sB[kc * PITCH + d] = vsrc[n];
        }
        // score tile -> final p; also transpose into sA[kc][r]
        for (int n = tid; n < TQ * TK; n += NTHREADS) {
            int r = n >> 7, kc = n & 127;
            size_t gi = (size_t)r * SP1 + 1 + (size_t)kt * TK + kc;
            float s = pb[gi];
            float pv = __expf(s - sM[r]) * sInv[r];
            pb[gi] = pv;
            sA[kc * PITCH + r] = pv;
        }
        __syncthreads();

#pragma unroll 4
        for (int kc = 0; kc < TK; ++kc) {
            float e[8], vv[8];
#pragma unroll
            for (int i = 0; i < 8; i++) e[i] = sA[kc * PITCH + ty + 16 * i];
#pragma unroll
            for (int j = 0; j < 8; j++) vv[j] = sB[kc * PITCH + tx + 16 * j];
#pragma unroll
            for (int i = 0; i < 8; i++)
#pragma unroll
                for (int j = 0; j < 8; j++)
                    oacc[i][j] = fmaf(e[i], vv[j], oacc[i][j]);
        }
    }

    // ---- P4: write out ----
    if (write_out) {
#pragma unroll
        for (int i = 0; i < 8; i++) {
            int r = ty + 16 * i;
#pragma unroll
            for (int j = 0; j < 8; j++) {
                int d = tx + 16 * j;
                ob[(size_t)r * DD + d] = oacc[i][j];
            }
        }
    }
}

extern "C" void kernel_launch(void* const* d_in, const int* in_sizes, int n_in,
                              void* d_out, int out_size)
{
    const float* q    = (const float*)d_in[0];
    const float* k    = (const float*)d_in[1];
    const float* v    = (const float*)d_in[2];
    const int*   mask = (const int*)d_in[3];

    const long OUT_N = (long)BB * SS * DD;           // 4,194,304
    const long P_N   = (long)BB * SS * SP1;          // 67,141,632

    float* out = (float*)d_out;
    float* p;
    int write_out = 1;
    if ((long)out_size == OUT_N + P_N) {
        p = out + OUT_N;                              // (out, p_attn)
    } else if ((long)out_size == P_N) {
        p = out;                                      // p_attn only
        write_out = 0;
    } else {
        p = out + OUT_N;                              // default: assume both
    }

    cudaFuncSetAttribute(qa_fp32_kernel,
                         cudaFuncAttributeMaxDynamicSharedMemorySize, SMEM_BYTES);

    dim3 grid(SS / TQ, BB);
    qa_fp32_kernel<<<grid, NTHREADS, SMEM_BYTES>>>(q, k, v, mask, out, p, write_out);
}